// round 5
// baseline (speedup 1.0000x reference)
#include <cuda_runtime.h>
#include <math.h>

#define NN 10000
#define NN2 10048          // 157 * 64, padded row count for scratch
#define NF 128
#define NH 64
#define MAXNNZ 2000000
#define CAP 16

// ---------------- scratch (device globals, no allocation) ----------------
__device__ __align__(16) float g_A[NN2 * NH];
__device__ __align__(16) float g_B[NN2 * NH];
__device__ __align__(16) float g_C[NN2 * NH];
__device__ __align__(16) float g_D[NN2 * NH];
__device__ __align__(16) float g_E[NN2 * NH];
__device__ __align__(16) float g_F[NN2 * NH];
__device__ __align__(16) float g_R[NN2 * NH];

__device__ int   g_rowbase[NN];
__device__ int   g_rownnz[NN];
__device__ int   g_cols[MAXNNZ];
__device__ float g_vals[MAXNNZ];
__device__ int   g_top;

__device__ __align__(16) float g_ssrc[NN];
__device__ __align__(16) float g_sdst[NN];
__device__ __align__(16) float g_part[250 * NH];
__device__ __align__(16) float g_Sall[NH];

// ---------------- reset ----------------
__global__ void k_reset() { g_top = 0; }

// ---------------- sparsify: dense adj -> per-row compacted (col,val) ----------------
__global__ void k_sparsify(const float* __restrict__ adj) {
    int row = blockIdx.x;
    const float4* rp = (const float4*)(adj + (size_t)row * NN);
    __shared__ int   scols[256 * CAP];
    __shared__ float svals[256 * CAP];
    __shared__ int   wsum[8];
    __shared__ int   sbase;

    int t = threadIdx.x;
    int lane = t & 31, wid = t >> 5;
    int c = 0;
    for (int j = t; j < NN / 4; j += 256) {
        float4 v = __ldcs(rp + j);
        int cb = j * 4;
        if (v.x != 0.f && c < CAP) { scols[t * CAP + c] = cb + 0; svals[t * CAP + c] = v.x; c++; }
        if (v.y != 0.f && c < CAP) { scols[t * CAP + c] = cb + 1; svals[t * CAP + c] = v.y; c++; }
        if (v.z != 0.f && c < CAP) { scols[t * CAP + c] = cb + 2; svals[t * CAP + c] = v.z; c++; }
        if (v.w != 0.f && c < CAP) { scols[t * CAP + c] = cb + 3; svals[t * CAP + c] = v.w; c++; }
    }
    int v = c;
    #pragma unroll
    for (int d = 1; d < 32; d <<= 1) {
        int n = __shfl_up_sync(0xffffffffu, v, d);
        if (lane >= d) v += n;
    }
    if (lane == 31) wsum[wid] = v;
    __syncthreads();
    int wbase = 0;
    #pragma unroll
    for (int i = 0; i < 8; i++) wbase += (i < wid) ? wsum[i] : 0;
    int excl = wbase + v - c;
    if (t == 0) {
        int tot = 0;
        #pragma unroll
        for (int i = 0; i < 8; i++) tot += wsum[i];
        int b = atomicAdd(&g_top, tot);
        g_rowbase[row] = b;
        g_rownnz[row]  = tot;
        sbase = b;
    }
    __syncthreads();
    int dst = sbase + excl;
    for (int i = 0; i < c; i++) {
        g_cols[dst + i] = scols[t * CAP + i];
        g_vals[dst + i] = svals[t * CAP + i];
    }
}

// ---------------- tiled GEMM: [NN,K] @ [K,64] (+bias, +relu), up to 3 instances ----------------
struct GemmArgs {
    const float* X[3];
    const float* W[3];
    const float* b[3];   // nullptr -> no bias
    float*       out[3];
    int          relu;   // bitmask per m
};

// block 256 threads, tile 64 rows x 64 cols, 4x4 register blocking, BK=32
template <int K>
__global__ void k_gemm(GemmArgs ga) {
    int m = blockIdx.y;
    const float* __restrict__ X = ga.X[m];
    const float* __restrict__ W = ga.W[m];
    const float* __restrict__ B = ga.b[m];
    float*       __restrict__ O = ga.out[m];
    bool relu = (ga.relu >> m) & 1;

    __shared__ float Xs[64 * 33];
    __shared__ float Ws[32 * 64];
    int tid = threadIdx.x;
    int r0 = blockIdx.x * 64;
    int tx = tid & 15;      // col group
    int ty = tid >> 4;      // row group [0,16)
    float acc[4][4] = {};

    for (int k0 = 0; k0 < K; k0 += 32) {
        #pragma unroll
        for (int i = 0; i < 8; i++) {
            int lr = (tid >> 5) + 8 * i;    // 0..63
            int rr = r0 + lr;
            float xv = 0.f;
            if (rr < NN) xv = X[(size_t)rr * K + k0 + (tid & 31)];
            Xs[lr * 33 + (tid & 31)] = xv;
        }
        #pragma unroll
        for (int i = 0; i < 8; i++) {
            int kk = (tid >> 6) + 4 * i;    // 0..31
            Ws[kk * 64 + (tid & 63)] = W[(size_t)(k0 + kk) * 64 + (tid & 63)];
        }
        __syncthreads();
        #pragma unroll
        for (int kk = 0; kk < 32; kk++) {
            float wv[4], xv[4];
            #pragma unroll
            for (int j = 0; j < 4; j++) wv[j] = Ws[kk * 64 + tx + 16 * j];
            #pragma unroll
            for (int i = 0; i < 4; i++) xv[i] = Xs[(ty * 4 + i) * 33 + kk];
            #pragma unroll
            for (int i = 0; i < 4; i++)
                #pragma unroll
                for (int j = 0; j < 4; j++)
                    acc[i][j] += xv[i] * wv[j];
        }
        __syncthreads();
    }
    #pragma unroll
    for (int i = 0; i < 4; i++) {
        int rr = r0 + ty * 4 + i;
        if (rr >= NN) continue;
        #pragma unroll
        for (int j = 0; j < 4; j++) {
            int c = tx + 16 * j;
            float vv = acc[i][j];
            if (B) vv += B[c];
            if (relu) vv = fmaxf(vv, 0.f);
            O[(size_t)rr * 64 + c] = vv;
        }
    }
}

// ---------------- fused SpMM (+bias+relu), both paths per block; optional scores epilogue ----------------
__global__ void k_spmm(const float* __restrict__ b0, const float* __restrict__ b1,
                       int layer2, const float* __restrict__ a) {
    int row = blockIdx.x;
    int tid = threadIdx.x;          // 64
    int m = tid >> 5, l = tid & 31; // warp0 = outcome, warp1 = treatment
    const float2* __restrict__ P  = (const float2*)(m ? g_B : g_A);
    const float2* __restrict__ bb = (const float2*)(m ? b1 : b0);
    float2*       __restrict__ O  = (float2*)(m ? g_D : g_C);
    int base = g_rowbase[row], nnz = g_rownnz[row];

    __shared__ int   scol[64];
    __shared__ float sval[64];
    __shared__ float srep[128];
    __shared__ float xr[2], xd[2];

    float2 a0 = {0.f, 0.f}, a1 = {0.f, 0.f};
    for (int c0 = 0; c0 < nnz; c0 += 64) {
        int n = min(64, nnz - c0);
        if (tid < n) { scol[tid] = g_cols[base + c0 + tid]; sval[tid] = g_vals[base + c0 + tid]; }
        __syncthreads();
        int e = 0;
        for (; e + 2 <= n; e += 2) {
            float2 p0 = P[(size_t)scol[e]     * 32 + l];
            float2 p1 = P[(size_t)scol[e + 1] * 32 + l];
            float v0 = sval[e], v1 = sval[e + 1];
            a0.x += v0 * p0.x; a0.y += v0 * p0.y;
            a1.x += v1 * p1.x; a1.y += v1 * p1.y;
        }
        if (e < n) {
            float2 p = P[(size_t)scol[e] * 32 + l];
            a0.x += sval[e] * p.x; a0.y += sval[e] * p.y;
        }
        __syncthreads();
    }
    float2 bv = bb[l];
    float2 acc;
    acc.x = fmaxf(a0.x + a1.x + bv.x, 0.f);
    acc.y = fmaxf(a0.y + a1.y + bv.y, 0.f);
    O[(size_t)row * 32 + l] = acc;

    if (layer2) {
        srep[m * 64 + 2 * l]     = acc.x;
        srep[m * 64 + 2 * l + 1] = acc.y;
        __syncthreads();
        float rs = srep[tid] * a[tid]       + srep[64 + tid] * a[64 + tid];
        float rd = srep[tid] * a[128 + tid] + srep[64 + tid] * a[192 + tid];
        #pragma unroll
        for (int o = 16; o; o >>= 1) {
            rs += __shfl_xor_sync(0xffffffffu, rs, o);
            rd += __shfl_xor_sync(0xffffffffu, rd, o);
        }
        if (l == 0) { xr[m] = rs; xd[m] = rd; }
        __syncthreads();
        if (tid == 0) { g_ssrc[row] = xr[0] + xr[1]; g_sdst[row] = xd[0] + xd[1]; }
    }
}

// ---------------- column sum of rep_t (deterministic 2-stage) ----------------
__global__ void k_colsum_part() {
    int b = blockIdx.x;   // 250 blocks x 40 rows
    int h = threadIdx.x;
    int r0 = b * 40;
    float acc = 0.f;
    #pragma unroll 4
    for (int r = r0; r < r0 + 40; r++) acc += g_D[(size_t)r * 64 + h];
    g_part[b * 64 + h] = acc;
}
__global__ void k_colsum_comb() {
    int h = threadIdx.x;
    float acc = 0.f;
    for (int b = 0; b < 250; b++) acc += g_part[b * 64 + h];
    g_Sall[h] = acc;
}

// ---------------- attention (analytic dense softmax over sparse scores), 1 warp/row ----------------
__global__ void k_att(float* __restrict__ dout) {
    int row = blockIdx.x * 2 + threadIdx.y;
    int l = threadIdx.x;
    int base = g_rowbase[row], nnz = g_rownnz[row];
    float si = g_ssrc[row];

    float lm = -1e30f;
    for (int e = l; e < nnz; e += 32)
        lm = fmaxf(lm, g_sdst[g_cols[base + e]]);
    #pragma unroll
    for (int o = 16; o; o >>= 1)
        lm = fmaxf(lm, __shfl_xor_sync(0xffffffffu, lm, o));
    float mm = fmaxf(si + lm, 0.f);

    const float2* __restrict__ D2 = (const float2*)g_D;
    float2 aW = {0.f, 0.f}, aR = {0.f, 0.f};
    float sw = 0.f;
    for (int e = 0; e < nnz; e++) {
        int cc = g_cols[base + e];
        float w = __expf(si + g_sdst[cc] - mm);
        float2 p = D2[(size_t)cc * 32 + l];
        aW.x += w * p.x; aW.y += w * p.y;
        aR.x += p.x;     aR.y += p.y;
        sw += w;
    }
    float em = __expf(-mm);
    float denom = (float)(NN - nnz) * em + sw;
    float2 S = ((const float2*)g_Sall)[l];
    float2 C = ((const float2*)g_C)[(size_t)row * 32 + l];
    float2 v;
    v.x = (em * (S.x - aR.x) + aW.x) / denom + C.x;
    v.y = (em * (S.y - aR.y) + aW.y) / denom + C.y;
    ((float2*)(dout + 10000))[(size_t)row * 32 + l] = v;
    ((float2*)g_R)[(size_t)row * 32 + l] = v;
}

// ---------------- final: y select + treatment sigmoid, 1 warp/row ----------------
__global__ void k_final(const int* __restrict__ t,
                        const float* __restrict__ Wo0, const float* __restrict__ bo0,
                        const float* __restrict__ Wo1, const float* __restrict__ bo1,
                        const float* __restrict__ Wpp2, const float* __restrict__ bpp2,
                        float* __restrict__ dout) {
    int row = blockIdx.x * 8 + threadIdx.y;
    int l = threadIdx.x;
    float2 c = ((const float2*)g_C)[(size_t)row * 32 + l];
    float2 f = ((const float2*)g_F)[(size_t)row * 32 + l];
    float2 e = ((const float2*)g_E)[(size_t)row * 32 + l];
    float2 w0 = ((const float2*)Wo0)[l];
    float2 w1 = ((const float2*)Wo1)[l];
    float4 q  = ((const float4*)Wpp2)[l];   // (W[2l,0],W[2l,1],W[2l+1,0],W[2l+1,1])

    float y0 = c.x * w0.x + c.y * w0.y;
    float y1 = f.x * w1.x + f.y * w1.y;
    float z0 = e.x * q.x + e.y * q.z;
    float z1 = e.x * q.y + e.y * q.w;
    #pragma unroll
    for (int o = 16; o; o >>= 1) {
        y0 += __shfl_xor_sync(0xffffffffu, y0, o);
        y1 += __shfl_xor_sync(0xffffffffu, y1, o);
        z0 += __shfl_xor_sync(0xffffffffu, z0, o);
        z1 += __shfl_xor_sync(0xffffffffu, z1, o);
    }
    if (l == 0) {
        dout[row] = (t[row] > 0) ? (y1 + bo1[0]) : (y0 + bo0[0]);
        dout[650000 + (size_t)row * 2 + 0] = 1.f / (1.f + __expf(-(z0 + bpp2[0])));
        dout[650000 + (size_t)row * 2 + 1] = 1.f / (1.f + __expf(-(z1 + bpp2[1])));
    }
}

// ---------------- launch ----------------
extern "C" void kernel_launch(void* const* d_in, const int* in_sizes, int n_in,
                              void* d_out, int out_size) {
    const float* x    = (const float*)d_in[0];
    const float* adj  = (const float*)d_in[1];
    const int*   t    = (const int*)d_in[2];
    const float* Wg0  = (const float*)d_in[3];
    const float* bg0  = (const float*)d_in[4];
    const float* Wg1  = (const float*)d_in[5];
    const float* bg1  = (const float*)d_in[6];
    const float* Wt0  = (const float*)d_in[7];
    const float* bt0  = (const float*)d_in[8];
    const float* Wt1  = (const float*)d_in[9];
    const float* bt1  = (const float*)d_in[10];
    const float* W000 = (const float*)d_in[11];
    const float* b000 = (const float*)d_in[12];
    const float* W001 = (const float*)d_in[13];
    const float* b001 = (const float*)d_in[14];
    const float* W100 = (const float*)d_in[15];
    const float* b100 = (const float*)d_in[16];
    const float* W101 = (const float*)d_in[17];
    const float* b101 = (const float*)d_in[18];
    const float* Wo0  = (const float*)d_in[19];
    const float* bo0  = (const float*)d_in[20];
    const float* Wo1  = (const float*)d_in[21];
    const float* bo1  = (const float*)d_in[22];
    const float* Wpp  = (const float*)d_in[23];
    const float* bpp  = (const float*)d_in[24];
    const float* Wpp2 = (const float*)d_in[25];
    const float* bpp2 = (const float*)d_in[26];
    const float* a    = (const float*)d_in[27];
    float* out = (float*)d_out;

    float* pA; cudaGetSymbolAddress((void**)&pA, g_A);
    float* pB; cudaGetSymbolAddress((void**)&pB, g_B);
    float* pC; cudaGetSymbolAddress((void**)&pC, g_C);
    float* pD; cudaGetSymbolAddress((void**)&pD, g_D);
    float* pE; cudaGetSymbolAddress((void**)&pE, g_E);
    float* pF; cudaGetSymbolAddress((void**)&pF, g_F);
    float* pR; cudaGetSymbolAddress((void**)&pR, g_R);

    k_reset<<<1, 1>>>();
    k_sparsify<<<NN, 256>>>(adj);

    // layer 1: P = x @ Wg0 / x @ Wt0
    {
        GemmArgs ga = {};
        ga.X[0] = x;   ga.X[1] = x;
        ga.W[0] = Wg0; ga.W[1] = Wt0;
        ga.out[0] = pA; ga.out[1] = pB;
        ga.relu = 0;
        k_gemm<128><<<dim3(157, 2), 256>>>(ga);
    }
    k_spmm<<<NN, 64>>>(bg0, bt0, 0, nullptr);

    // layer 2
    {
        GemmArgs ga = {};
        ga.X[0] = pC;  ga.X[1] = pD;
        ga.W[0] = Wg1; ga.W[1] = Wt1;
        ga.out[0] = pA; ga.out[1] = pB;
        ga.relu = 0;
        k_gemm<64><<<dim3(157, 2), 256>>>(ga);
    }
    k_spmm<<<NN, 64>>>(bg1, bt1, 1, a);   // + fused scores

    k_colsum_part<<<250, 64>>>();
    k_colsum_comb<<<1, 64>>>();
    k_att<<<5000, dim3(32, 2)>>>(out);

    // heads stage 1: relu(rep_out@W000+b000), relu(rep_out@W100+b100), rep_t@Wpp+bpp
    {
        GemmArgs ga = {};
        ga.X[0] = pR;   ga.X[1] = pR;   ga.X[2] = pD;
        ga.W[0] = W000; ga.W[1] = W100; ga.W[2] = Wpp;
        ga.b[0] = b000; ga.b[1] = b100; ga.b[2] = bpp;
        ga.out[0] = pA; ga.out[1] = pB; ga.out[2] = pE;
        ga.relu = 0b011;
        k_gemm<64><<<dim3(157, 3), 256>>>(ga);
    }
    // heads stage 2: relu(h@W001+b001), relu(h@W101+b101)
    {
        GemmArgs ga = {};
        ga.X[0] = pA;   ga.X[1] = pB;
        ga.W[0] = W001; ga.W[1] = W101;
        ga.b[0] = b001; ga.b[1] = b101;
        ga.out[0] = pC; ga.out[1] = pF;
        ga.relu = 0b11;
        k_gemm<64><<<dim3(157, 2), 256>>>(ga);
    }
    k_final<<<1250, dim3(32, 8)>>>(t, Wo0, bo0, Wo1, bo1, Wpp2, bpp2, out);
}

// round 6
// speedup vs baseline: 1.4508x; 1.4508x over previous
#include <cuda_runtime.h>
#include <math.h>

#define NN 10000
#define NN2 10048          // 157 * 64, padded row count for scratch
#define NF 128
#define NH 64
#define MAXNNZ 2000000

// ---------------- scratch (device globals, no allocation) ----------------
__device__ __align__(16) float g_A[NN2 * NH];
__device__ __align__(16) float g_B[NN2 * NH];
__device__ __align__(16) float g_C[NN2 * NH];
__device__ __align__(16) float g_D[NN2 * NH];
__device__ __align__(16) float g_E[NN2 * NH];
__device__ __align__(16) float g_F[NN2 * NH];
__device__ __align__(16) float g_R[NN2 * NH];

struct __align__(8) Edge { int c; float v; };

__device__ int   g_rowbase[NN];
__device__ int   g_rownnz[NN];
__device__ Edge  g_edge[MAXNNZ];
__device__ int   g_top = 0;

__device__ __align__(16) float g_ssrc[NN];
__device__ __align__(16) float g_sdst[NN];
__device__ __align__(16) float g_part[250 * NH];
__device__ __align__(16) float g_Sall[NH];

// ---------------- sparsify: dense adj -> per-row packed edges ----------------
// Register-resident: 10 float4 loads issued unconditionally up front (MLP=10),
// then count/scan/emit purely from registers. No value staging in smem.
__global__ void k_sparsify(const float* __restrict__ adj) {
    int row = blockIdx.x;
    const float4* rp = (const float4*)(adj + (size_t)row * NN);
    int t = threadIdx.x;
    int lane = t & 31, wid = t >> 5;

    float4 v[10];
    #pragma unroll
    for (int i = 0; i < 10; i++) {
        int j = t + 256 * i;
        if (j < NN / 4) v[i] = __ldcs(rp + j);
        else            v[i] = make_float4(0.f, 0.f, 0.f, 0.f);
    }

    int c = 0;
    #pragma unroll
    for (int i = 0; i < 10; i++)
        c += (v[i].x != 0.f) + (v[i].y != 0.f) + (v[i].z != 0.f) + (v[i].w != 0.f);

    // block-wide exclusive scan of counts
    __shared__ int wsum[8];
    __shared__ int sbase;
    int s = c;
    #pragma unroll
    for (int d = 1; d < 32; d <<= 1) {
        int n = __shfl_up_sync(0xffffffffu, s, d);
        if (lane >= d) s += n;
    }
    if (lane == 31) wsum[wid] = s;
    __syncthreads();
    int wbase = 0;
    #pragma unroll
    for (int i = 0; i < 8; i++) wbase += (i < wid) ? wsum[i] : 0;
    int excl = wbase + s - c;
    if (t == 0) {
        int tot = 0;
        #pragma unroll
        for (int i = 0; i < 8; i++) tot += wsum[i];
        int b = atomicAdd(&g_top, tot);
        g_rowbase[row] = b;
        g_rownnz[row]  = tot;
        sbase = b;
    }
    __syncthreads();

    int dst = sbase + excl;
    #pragma unroll
    for (int i = 0; i < 10; i++) {
        int cb = (t + 256 * i) * 4;
        if (v[i].x != 0.f) { g_edge[dst].c = cb + 0; g_edge[dst].v = v[i].x; dst++; }
        if (v[i].y != 0.f) { g_edge[dst].c = cb + 1; g_edge[dst].v = v[i].y; dst++; }
        if (v[i].z != 0.f) { g_edge[dst].c = cb + 2; g_edge[dst].v = v[i].z; dst++; }
        if (v[i].w != 0.f) { g_edge[dst].c = cb + 3; g_edge[dst].v = v[i].w; dst++; }
    }
}

// ---------------- tiled GEMM: [NN,K] @ [K,64] (+bias, +relu), up to 3 instances ----------------
struct GemmArgs {
    const float* X[3];
    const float* W[3];
    const float* b[3];   // nullptr -> no bias
    float*       out[3];
    int          relu;   // bitmask per m
};

// block 256 threads, tile 64 rows x 64 cols, 4x4 register blocking, BK=32
template <int K>
__global__ void k_gemm(GemmArgs ga) {
    int m = blockIdx.y;
    const float* __restrict__ X = ga.X[m];
    const float* __restrict__ W = ga.W[m];
    const float* __restrict__ B = ga.b[m];
    float*       __restrict__ O = ga.out[m];
    bool relu = (ga.relu >> m) & 1;

    __shared__ float Xs[64 * 33];
    __shared__ float Ws[32 * 64];
    int tid = threadIdx.x;
    int r0 = blockIdx.x * 64;
    int tx = tid & 15;
    int ty = tid >> 4;
    float acc[4][4] = {};

    for (int k0 = 0; k0 < K; k0 += 32) {
        #pragma unroll
        for (int i = 0; i < 8; i++) {
            int lr = (tid >> 5) + 8 * i;
            int rr = r0 + lr;
            float xv = 0.f;
            if (rr < NN) xv = X[(size_t)rr * K + k0 + (tid & 31)];
            Xs[lr * 33 + (tid & 31)] = xv;
        }
        #pragma unroll
        for (int i = 0; i < 8; i++) {
            int kk = (tid >> 6) + 4 * i;
            Ws[kk * 64 + (tid & 63)] = W[(size_t)(k0 + kk) * 64 + (tid & 63)];
        }
        __syncthreads();
        #pragma unroll
        for (int kk = 0; kk < 32; kk++) {
            float wv[4], xv[4];
            #pragma unroll
            for (int j = 0; j < 4; j++) wv[j] = Ws[kk * 64 + tx + 16 * j];
            #pragma unroll
            for (int i = 0; i < 4; i++) xv[i] = Xs[(ty * 4 + i) * 33 + kk];
            #pragma unroll
            for (int i = 0; i < 4; i++)
                #pragma unroll
                for (int j = 0; j < 4; j++)
                    acc[i][j] += xv[i] * wv[j];
        }
        __syncthreads();
    }
    #pragma unroll
    for (int i = 0; i < 4; i++) {
        int rr = r0 + ty * 4 + i;
        if (rr >= NN) continue;
        #pragma unroll
        for (int j = 0; j < 4; j++) {
            int c = tx + 16 * j;
            float vv = acc[i][j];
            if (B) vv += B[c];
            if (relu) vv = fmaxf(vv, 0.f);
            O[(size_t)rr * 64 + c] = vv;
        }
    }
}

// ---------------- fused SpMM (+bias+relu), both paths per block; optional scores epilogue ----------------
__global__ void k_spmm(const float* __restrict__ b0, const float* __restrict__ b1,
                       int layer2, const float* __restrict__ a) {
    int row = blockIdx.x;
    int tid = threadIdx.x;          // 64
    int m = tid >> 5, l = tid & 31; // warp0 = outcome, warp1 = treatment
    const float2* __restrict__ P  = (const float2*)(m ? g_B : g_A);
    const float2* __restrict__ bb = (const float2*)(m ? b1 : b0);
    float2*       __restrict__ O  = (float2*)(m ? g_D : g_C);
    int base = g_rowbase[row], nnz = g_rownnz[row];

    __shared__ Edge  se[64];
    __shared__ float srep[128];
    __shared__ float xr[2], xd[2];

    float2 a0 = {0.f, 0.f}, a1 = {0.f, 0.f}, a2 = {0.f, 0.f}, a3 = {0.f, 0.f};
    for (int c0 = 0; c0 < nnz; c0 += 64) {
        int n = min(64, nnz - c0);
        if (tid < n) se[tid] = g_edge[base + c0 + tid];
        __syncthreads();
        int e = 0;
        for (; e + 4 <= n; e += 4) {
            Edge e0 = se[e], e1 = se[e + 1], e2 = se[e + 2], e3 = se[e + 3];
            float2 p0 = P[(size_t)e0.c * 32 + l];
            float2 p1 = P[(size_t)e1.c * 32 + l];
            float2 p2 = P[(size_t)e2.c * 32 + l];
            float2 p3 = P[(size_t)e3.c * 32 + l];
            a0.x += e0.v * p0.x; a0.y += e0.v * p0.y;
            a1.x += e1.v * p1.x; a1.y += e1.v * p1.y;
            a2.x += e2.v * p2.x; a2.y += e2.v * p2.y;
            a3.x += e3.v * p3.x; a3.y += e3.v * p3.y;
        }
        for (; e < n; e++) {
            Edge ee = se[e];
            float2 p = P[(size_t)ee.c * 32 + l];
            a0.x += ee.v * p.x; a0.y += ee.v * p.y;
        }
        __syncthreads();
    }
    float2 bv = bb[l];
    float2 acc;
    acc.x = fmaxf(a0.x + a1.x + a2.x + a3.x + bv.x, 0.f);
    acc.y = fmaxf(a0.y + a1.y + a2.y + a3.y + bv.y, 0.f);
    O[(size_t)row * 32 + l] = acc;

    if (layer2) {
        srep[m * 64 + 2 * l]     = acc.x;
        srep[m * 64 + 2 * l + 1] = acc.y;
        __syncthreads();
        float rs = srep[tid] * a[tid]       + srep[64 + tid] * a[64 + tid];
        float rd = srep[tid] * a[128 + tid] + srep[64 + tid] * a[192 + tid];
        #pragma unroll
        for (int o = 16; o; o >>= 1) {
            rs += __shfl_xor_sync(0xffffffffu, rs, o);
            rd += __shfl_xor_sync(0xffffffffu, rd, o);
        }
        if (l == 0) { xr[m] = rs; xd[m] = rd; }
        __syncthreads();
        if (tid == 0) { g_ssrc[row] = xr[0] + xr[1]; g_sdst[row] = xd[0] + xd[1]; }
    }
}

// ---------------- column sum of rep_t (deterministic 2-stage) ----------------
__global__ void k_colsum_part() {
    int b = blockIdx.x;   // 250 blocks x 40 rows
    int h = threadIdx.x;
    int r0 = b * 40;
    float acc = 0.f;
    #pragma unroll 4
    for (int r = r0; r < r0 + 40; r++) acc += g_D[(size_t)r * 64 + h];
    g_part[b * 64 + h] = acc;
}
__global__ void k_colsum_comb() {
    int h = threadIdx.x;
    float acc = 0.f;
    for (int b = 0; b < 250; b++) acc += g_part[b * 64 + h];
    g_Sall[h] = acc;
}

// ---------------- attention (analytic dense softmax over sparse scores), 1 warp/row ----------------
__global__ void k_att(float* __restrict__ dout) {
    int row = blockIdx.x * 2 + threadIdx.y;
    int l = threadIdx.x;
    int base = g_rowbase[row], nnz = g_rownnz[row];
    float si = g_ssrc[row];

    float lm = -1e30f;
    for (int e = l; e < nnz; e += 32)
        lm = fmaxf(lm, g_sdst[g_edge[base + e].c]);
    #pragma unroll
    for (int o = 16; o; o >>= 1)
        lm = fmaxf(lm, __shfl_xor_sync(0xffffffffu, lm, o));
    float mm = fmaxf(si + lm, 0.f);

    const float2* __restrict__ D2 = (const float2*)g_D;
    float2 aW = {0.f, 0.f}, aR = {0.f, 0.f};
    float sw = 0.f;
    for (int e = 0; e < nnz; e++) {
        int cc = g_edge[base + e].c;
        float w = __expf(si + g_sdst[cc] - mm);
        float2 p = D2[(size_t)cc * 32 + l];
        aW.x += w * p.x; aW.y += w * p.y;
        aR.x += p.x;     aR.y += p.y;
        sw += w;
    }
    float em = __expf(-mm);
    float denom = (float)(NN - nnz) * em + sw;
    float2 S = ((const float2*)g_Sall)[l];
    float2 C = ((const float2*)g_C)[(size_t)row * 32 + l];
    float2 v;
    v.x = (em * (S.x - aR.x) + aW.x) / denom + C.x;
    v.y = (em * (S.y - aR.y) + aW.y) / denom + C.y;
    ((float2*)(dout + 10000))[(size_t)row * 32 + l] = v;
    ((float2*)g_R)[(size_t)row * 32 + l] = v;
}

// ---------------- final: y select + treatment sigmoid, 1 warp/row ----------------
__global__ void k_final(const int* __restrict__ t,
                        const float* __restrict__ Wo0, const float* __restrict__ bo0,
                        const float* __restrict__ Wo1, const float* __restrict__ bo1,
                        const float* __restrict__ Wpp2, const float* __restrict__ bpp2,
                        float* __restrict__ dout) {
    int row = blockIdx.x * 8 + threadIdx.y;
    int l = threadIdx.x;
    float2 c = ((const float2*)g_C)[(size_t)row * 32 + l];
    float2 f = ((const float2*)g_F)[(size_t)row * 32 + l];
    float2 e = ((const float2*)g_E)[(size_t)row * 32 + l];
    float2 w0 = ((const float2*)Wo0)[l];
    float2 w1 = ((const float2*)Wo1)[l];
    float4 q  = ((const float4*)Wpp2)[l];

    float y0 = c.x * w0.x + c.y * w0.y;
    float y1 = f.x * w1.x + f.y * w1.y;
    float z0 = e.x * q.x + e.y * q.z;
    float z1 = e.x * q.y + e.y * q.w;
    #pragma unroll
    for (int o = 16; o; o >>= 1) {
        y0 += __shfl_xor_sync(0xffffffffu, y0, o);
        y1 += __shfl_xor_sync(0xffffffffu, y1, o);
        z0 += __shfl_xor_sync(0xffffffffu, z0, o);
        z1 += __shfl_xor_sync(0xffffffffu, z1, o);
    }
    if (l == 0) {
        dout[row] = (t[row] > 0) ? (y1 + bo1[0]) : (y0 + bo0[0]);
        dout[650000 + (size_t)row * 2 + 0] = 1.f / (1.f + __expf(-(z0 + bpp2[0])));
        dout[650000 + (size_t)row * 2 + 1] = 1.f / (1.f + __expf(-(z1 + bpp2[1])));
    }
    // reset edge-pool top for the next graph replay (g_top statically inits to 0
    // for the very first run; every run ends by re-arming it)
    if (blockIdx.x == 0 && threadIdx.y == 0 && l == 0) g_top = 0;
}

// ---------------- launch ----------------
extern "C" void kernel_launch(void* const* d_in, const int* in_sizes, int n_in,
                              void* d_out, int out_size) {
    const float* x    = (const float*)d_in[0];
    const float* adj  = (const float*)d_in[1];
    const int*   t    = (const int*)d_in[2];
    const float* Wg0  = (const float*)d_in[3];
    const float* bg0  = (const float*)d_in[4];
    const float* Wg1  = (const float*)d_in[5];
    const float* bg1  = (const float*)d_in[6];
    const float* Wt0  = (const float*)d_in[7];
    const float* bt0  = (const float*)d_in[8];
    const float* Wt1  = (const float*)d_in[9];
    const float* bt1  = (const float*)d_in[10];
    const float* W000 = (const float*)d_in[11];
    const float* b000 = (const float*)d_in[12];
    const float* W001 = (const float*)d_in[13];
    const float* b001 = (const float*)d_in[14];
    const float* W100 = (const float*)d_in[15];
    const float* b100 = (const float*)d_in[16];
    const float* W101 = (const float*)d_in[17];
    const float* b101 = (const float*)d_in[18];
    const float* Wo0  = (const float*)d_in[19];
    const float* bo0  = (const float*)d_in[20];
    const float* Wo1  = (const float*)d_in[21];
    const float* bo1  = (const float*)d_in[22];
    const float* Wpp  = (const float*)d_in[23];
    const float* bpp  = (const float*)d_in[24];
    const float* Wpp2 = (const float*)d_in[25];
    const float* bpp2 = (const float*)d_in[26];
    const float* a    = (const float*)d_in[27];
    float* out = (float*)d_out;

    float* pA; cudaGetSymbolAddress((void**)&pA, g_A);
    float* pB; cudaGetSymbolAddress((void**)&pB, g_B);
    float* pC; cudaGetSymbolAddress((void**)&pC, g_C);
    float* pD; cudaGetSymbolAddress((void**)&pD, g_D);
    float* pE; cudaGetSymbolAddress((void**)&pE, g_E);
    float* pF; cudaGetSymbolAddress((void**)&pF, g_F);
    float* pR; cudaGetSymbolAddress((void**)&pR, g_R);

    k_sparsify<<<NN, 256>>>(adj);

    // layer 1: P = x @ Wg0 / x @ Wt0
    {
        GemmArgs ga = {};
        ga.X[0] = x;   ga.X[1] = x;
        ga.W[0] = Wg0; ga.W[1] = Wt0;
        ga.out[0] = pA; ga.out[1] = pB;
        ga.relu = 0;
        k_gemm<128><<<dim3(157, 2), 256>>>(ga);
    }
    k_spmm<<<NN, 64>>>(bg0, bt0, 0, nullptr);

    // layer 2
    {
        GemmArgs ga = {};
        ga.X[0] = pC;  ga.X[1] = pD;
        ga.W[0] = Wg1; ga.W[1] = Wt1;
        ga.out[0] = pA; ga.out[1] = pB;
        ga.relu = 0;
        k_gemm<64><<<dim3(157, 2), 256>>>(ga);
    }
    k_spmm<<<NN, 64>>>(bg1, bt1, 1, a);   // + fused scores

    k_colsum_part<<<250, 64>>>();
    k_colsum_comb<<<1, 64>>>();
    k_att<<<5000, dim3(32, 2)>>>(out);

    // heads stage 1: relu(rep_out@W000+b000), relu(rep_out@W100+b100), rep_t@Wpp+bpp
    {
        GemmArgs ga = {};
        ga.X[0] = pR;   ga.X[1] = pR;   ga.X[2] = pD;
        ga.W[0] = W000; ga.W[1] = W100; ga.W[2] = Wpp;
        ga.b[0] = b000; ga.b[1] = b100; ga.b[2] = bpp;
        ga.out[0] = pA; ga.out[1] = pB; ga.out[2] = pE;
        ga.relu = 0b011;
        k_gemm<64><<<dim3(157, 3), 256>>>(ga);
    }
    // heads stage 2: relu(h@W001+b001), relu(h@W101+b101)
    {
        GemmArgs ga = {};
        ga.X[0] = pA;   ga.X[1] = pB;
        ga.W[0] = W001; ga.W[1] = W101;
        ga.b[0] = b001; ga.b[1] = b101;
        ga.out[0] = pC; ga.out[1] = pF;
        ga.relu = 0b11;
        k_gemm<64><<<dim3(157, 2), 256>>>(ga);
    }
    k_final<<<1250, dim3(32, 8)>>>(t, Wo0, bo0, Wo1, bo1, Wpp2, bpp2, out);
}

// round 7
// speedup vs baseline: 1.5397x; 1.0612x over previous
#include <cuda_runtime.h>
#include <math.h>

#define NN 10000
#define NN2 10048          // padded row count for scratch
#define NF 128
#define NH 64
#define MAXNNZ 2000000

// ---------------- scratch (device globals, no allocation) ----------------
__device__ __align__(16) float g_A[NN2 * NH];
__device__ __align__(16) float g_B[NN2 * NH];
__device__ __align__(16) float g_C[NN2 * NH];
__device__ __align__(16) float g_D[NN2 * NH];
__device__ __align__(16) float g_R[NN2 * NH];

struct __align__(8) Edge { int c; float v; };

__device__ int   g_rowbase[NN];
__device__ int   g_rownnz[NN];
__device__ Edge  g_edge[MAXNNZ];
__device__ int   g_top = 0;

__device__ __align__(16) float g_ssrc[NN];
__device__ __align__(16) float g_sdst[NN];
__device__ __align__(16) float g_part[250 * NH];
__device__ __align__(16) float g_Sall[NH];

// ---------------- sparsify: dense adj -> per-row packed edges ----------------
__global__ void k_sparsify(const float* __restrict__ adj) {
    int row = blockIdx.x;
    const float4* rp = (const float4*)(adj + (size_t)row * NN);
    int t = threadIdx.x;
    int lane = t & 31, wid = t >> 5;

    float4 v[10];
    #pragma unroll
    for (int i = 0; i < 10; i++) {
        int j = t + 256 * i;
        if (j < NN / 4) v[i] = __ldcs(rp + j);
        else            v[i] = make_float4(0.f, 0.f, 0.f, 0.f);
    }

    int c = 0;
    #pragma unroll
    for (int i = 0; i < 10; i++)
        c += (v[i].x != 0.f) + (v[i].y != 0.f) + (v[i].z != 0.f) + (v[i].w != 0.f);

    __shared__ int wsum[8];
    __shared__ int sbase;
    int s = c;
    #pragma unroll
    for (int d = 1; d < 32; d <<= 1) {
        int n = __shfl_up_sync(0xffffffffu, s, d);
        if (lane >= d) s += n;
    }
    if (lane == 31) wsum[wid] = s;
    __syncthreads();
    int wbase = 0;
    #pragma unroll
    for (int i = 0; i < 8; i++) wbase += (i < wid) ? wsum[i] : 0;
    int excl = wbase + s - c;
    if (t == 0) {
        int tot = 0;
        #pragma unroll
        for (int i = 0; i < 8; i++) tot += wsum[i];
        int b = atomicAdd(&g_top, tot);
        g_rowbase[row] = b;
        g_rownnz[row]  = tot;
        sbase = b;
    }
    __syncthreads();

    int dst = sbase + excl;
    #pragma unroll
    for (int i = 0; i < 10; i++) {
        int cb = (t + 256 * i) * 4;
        if (v[i].x != 0.f) { g_edge[dst].c = cb + 0; g_edge[dst].v = v[i].x; dst++; }
        if (v[i].y != 0.f) { g_edge[dst].c = cb + 1; g_edge[dst].v = v[i].y; dst++; }
        if (v[i].z != 0.f) { g_edge[dst].c = cb + 2; g_edge[dst].v = v[i].z; dst++; }
        if (v[i].w != 0.f) { g_edge[dst].c = cb + 3; g_edge[dst].v = v[i].w; dst++; }
    }
}

// ---------------- tiled GEMM: [NN,K] @ [K,64], 32-row tiles, 2 instances ----------------
struct GemmArgs {
    const float* X[2];
    const float* W[2];
    float*       out[2];
};

// block 256 threads: tx=tid&15 -> cols tx*4..+3 (adjacent), ty=tid>>4 -> rows ty*2,ty*2+1
template <int K>
__global__ void __launch_bounds__(256) k_gemm(GemmArgs ga) {
    int m = blockIdx.y;
    const float* __restrict__ X = ga.X[m];
    const float* __restrict__ W = ga.W[m];
    float*       __restrict__ O = ga.out[m];

    __shared__ float Xs[32 * 65];
    __shared__ float Ws[64 * 64];
    int tid = threadIdx.x;
    int tx = tid & 15, ty = tid >> 4;
    int r0 = blockIdx.x * 32;
    float acc[2][4] = {};

    for (int k0 = 0; k0 < K; k0 += 64) {
        {   // weights chunk: rows k0..k0+63 of [K,64], contiguous
            const float4* s = (const float4*)(W + (size_t)k0 * 64);
            float4* d = (float4*)Ws;
            #pragma unroll
            for (int i = 0; i < 4; i++) d[tid + 256 * i] = s[tid + 256 * i];
        }
        #pragma unroll
        for (int i = 0; i < 2; i++) {
            int e = tid + 256 * i;      // 0..511 float4 index (32 rows x 16 f4)
            int row = e >> 4, c4 = e & 15;
            int rr = r0 + row;
            float4 v = make_float4(0.f, 0.f, 0.f, 0.f);
            if (rr < NN) v = ((const float4*)(X + (size_t)rr * K + k0))[c4];
            Xs[row * 65 + c4 * 4 + 0] = v.x;
            Xs[row * 65 + c4 * 4 + 1] = v.y;
            Xs[row * 65 + c4 * 4 + 2] = v.z;
            Xs[row * 65 + c4 * 4 + 3] = v.w;
        }
        __syncthreads();
        #pragma unroll 4
        for (int k = 0; k < 64; k++) {
            float4 wv = *(const float4*)&Ws[k * 64 + tx * 4];
            float x0 = Xs[(ty * 2) * 65 + k];
            float x1 = Xs[(ty * 2 + 1) * 65 + k];
            acc[0][0] += x0 * wv.x; acc[0][1] += x0 * wv.y;
            acc[0][2] += x0 * wv.z; acc[0][3] += x0 * wv.w;
            acc[1][0] += x1 * wv.x; acc[1][1] += x1 * wv.y;
            acc[1][2] += x1 * wv.z; acc[1][3] += x1 * wv.w;
        }
        __syncthreads();
    }
    #pragma unroll
    for (int i = 0; i < 2; i++) {
        int rr = r0 + ty * 2 + i;
        if (rr >= NN) continue;
        float4 o = make_float4(acc[i][0], acc[i][1], acc[i][2], acc[i][3]);
        *(float4*)(O + (size_t)rr * 64 + tx * 4) = o;
    }
}

// ---------------- fused SpMM (+bias+relu), both paths per block; optional scores epilogue ----------------
__global__ void k_spmm(const float* __restrict__ b0, const float* __restrict__ b1,
                       int layer2, const float* __restrict__ a) {
    int row = blockIdx.x;
    int tid = threadIdx.x;          // 64
    int m = tid >> 5, l = tid & 31;
    const float2* __restrict__ P  = (const float2*)(m ? g_B : g_A);
    const float2* __restrict__ bb = (const float2*)(m ? b1 : b0);
    float2*       __restrict__ O  = (float2*)(m ? g_D : g_C);
    int base = g_rowbase[row], nnz = g_rownnz[row];

    __shared__ Edge  se[64];
    __shared__ float srep[128];
    __shared__ float xr[2], xd[2];

    float2 a0 = {0.f, 0.f}, a1 = {0.f, 0.f}, a2 = {0.f, 0.f}, a3 = {0.f, 0.f};
    for (int c0 = 0; c0 < nnz; c0 += 64) {
        int n = min(64, nnz - c0);
        if (tid < n) se[tid] = g_edge[base + c0 + tid];
        __syncthreads();
        int e = 0;
        for (; e + 4 <= n; e += 4) {
            Edge e0 = se[e], e1 = se[e + 1], e2 = se[e + 2], e3 = se[e + 3];
            float2 p0 = P[(size_t)e0.c * 32 + l];
            float2 p1 = P[(size_t)e1.c * 32 + l];
            float2 p2 = P[(size_t)e2.c * 32 + l];
            float2 p3 = P[(size_t)e3.c * 32 + l];
            a0.x += e0.v * p0.x; a0.y += e0.v * p0.y;
            a1.x += e1.v * p1.x; a1.y += e1.v * p1.y;
            a2.x += e2.v * p2.x; a2.y += e2.v * p2.y;
            a3.x += e3.v * p3.x; a3.y += e3.v * p3.y;
        }
        for (; e < n; e++) {
            Edge ee = se[e];
            float2 p = P[(size_t)ee.c * 32 + l];
            a0.x += ee.v * p.x; a0.y += ee.v * p.y;
        }
        __syncthreads();
    }
    float2 bv = bb[l];
    float2 acc;
    acc.x = fmaxf(a0.x + a1.x + a2.x + a3.x + bv.x, 0.f);
    acc.y = fmaxf(a0.y + a1.y + a2.y + a3.y + bv.y, 0.f);
    O[(size_t)row * 32 + l] = acc;

    if (layer2) {
        srep[m * 64 + 2 * l]     = acc.x;
        srep[m * 64 + 2 * l + 1] = acc.y;
        __syncthreads();
        float rs = srep[tid] * a[tid]       + srep[64 + tid] * a[64 + tid];
        float rd = srep[tid] * a[128 + tid] + srep[64 + tid] * a[192 + tid];
        #pragma unroll
        for (int o = 16; o; o >>= 1) {
            rs += __shfl_xor_sync(0xffffffffu, rs, o);
            rd += __shfl_xor_sync(0xffffffffu, rd, o);
        }
        if (l == 0) { xr[m] = rs; xd[m] = rd; }
        __syncthreads();
        if (tid == 0) { g_ssrc[row] = xr[0] + xr[1]; g_sdst[row] = xd[0] + xd[1]; }
    }
}

// ---------------- column sum of rep_t (deterministic 2-stage) ----------------
__global__ void k_colsum_part() {
    int b = blockIdx.x;   // 250 blocks x 40 rows
    int h = threadIdx.x;
    int r0 = b * 40;
    float acc = 0.f;
    #pragma unroll 4
    for (int r = r0; r < r0 + 40; r++) acc += g_D[(size_t)r * 64 + h];
    g_part[b * 64 + h] = acc;
}
__global__ void k_colsum_comb() {
    int h = threadIdx.x;
    float acc = 0.f;
    for (int b = 0; b < 250; b++) acc += g_part[b * 64 + h];
    g_Sall[h] = acc;
}

// ---------------- attention (analytic dense softmax over sparse scores), 1 warp/row ----------------
__global__ void k_att(float* __restrict__ dout) {
    int row = blockIdx.x * 2 + threadIdx.y;
    int l = threadIdx.x;
    int base = g_rowbase[row], nnz = g_rownnz[row];
    float si = g_ssrc[row];

    float lm = -1e30f;
    for (int e = l; e < nnz; e += 32)
        lm = fmaxf(lm, g_sdst[g_edge[base + e].c]);
    #pragma unroll
    for (int o = 16; o; o >>= 1)
        lm = fmaxf(lm, __shfl_xor_sync(0xffffffffu, lm, o));
    float mm = fmaxf(si + lm, 0.f);

    const float2* __restrict__ D2 = (const float2*)g_D;
    float2 aW = {0.f, 0.f}, aR = {0.f, 0.f};
    float sw = 0.f;
    for (int e = 0; e < nnz; e++) {
        int cc = g_edge[base + e].c;
        float w = __expf(si + g_sdst[cc] - mm);
        float2 p = D2[(size_t)cc * 32 + l];
        aW.x += w * p.x; aW.y += w * p.y;
        aR.x += p.x;     aR.y += p.y;
        sw += w;
    }
    float em = __expf(-mm);
    float denom = (float)(NN - nnz) * em + sw;
    float2 S = ((const float2*)g_Sall)[l];
    float2 C = ((const float2*)g_C)[(size_t)row * 32 + l];
    float2 v;
    v.x = (em * (S.x - aR.x) + aW.x) / denom + C.x;
    v.y = (em * (S.y - aR.y) + aW.y) / denom + C.y;
    ((float2*)(dout + 10000))[(size_t)row * 32 + l] = v;
    ((float2*)g_R)[(size_t)row * 32 + l] = v;
}

// ---------------- fused heads: all 5 small GEMMs + outputs, per 64-row tile ----------------
__global__ void __launch_bounds__(256) k_heads(
        const int* __restrict__ t,
        const float* __restrict__ W000, const float* __restrict__ b000,
        const float* __restrict__ W001, const float* __restrict__ b001,
        const float* __restrict__ W100, const float* __restrict__ b100,
        const float* __restrict__ W101, const float* __restrict__ b101,
        const float* __restrict__ Wo0,  const float* __restrict__ bo0,
        const float* __restrict__ Wo1,  const float* __restrict__ bo1,
        const float* __restrict__ Wpp,  const float* __restrict__ bpp,
        const float* __restrict__ Wpp2, const float* __restrict__ bpp2,
        float* __restrict__ dout) {
    __shared__ float U[64 * 65];
    __shared__ float V[64 * 65];
    __shared__ float Ws[64 * 64];
    __shared__ float sWv[64];
    __shared__ float yy[2][64];

    int tid = threadIdx.x;
    int tx = tid & 15, ty = tid >> 4;
    int r0 = blockIdx.x * 64;

    // --- helpers (expanded manually via lambdas) ---
    auto loadW = [&](const float* W) {
        const float4* s = (const float4*)W;
        float4* d = (float4*)Ws;
        #pragma unroll
        for (int i = 0; i < 4; i++) d[tid + 256 * i] = s[tid + 256 * i];
    };
    auto loadX = [&](const float* X) {
        #pragma unroll
        for (int i = 0; i < 4; i++) {
            int e = tid + 256 * i;        // 0..1023 f4 idx (64 rows x 16 f4)
            int row = e >> 4, c4 = e & 15;
            float4 v = ((const float4*)(X + (size_t)(r0 + row) * 64))[c4];
            U[row * 65 + c4 * 4 + 0] = v.x;
            U[row * 65 + c4 * 4 + 1] = v.y;
            U[row * 65 + c4 * 4 + 2] = v.z;
            U[row * 65 + c4 * 4 + 3] = v.w;
        }
    };
    auto stage = [&](const float* in, float* outp, const float* b, bool relu) {
        float acc[4][4] = {};
        #pragma unroll 4
        for (int k = 0; k < 64; k++) {
            float4 wv = *(const float4*)&Ws[k * 64 + tx * 4];
            float xv[4];
            #pragma unroll
            for (int i = 0; i < 4; i++) xv[i] = in[(ty * 4 + i) * 65 + k];
            #pragma unroll
            for (int i = 0; i < 4; i++) {
                acc[i][0] += xv[i] * wv.x; acc[i][1] += xv[i] * wv.y;
                acc[i][2] += xv[i] * wv.z; acc[i][3] += xv[i] * wv.w;
            }
        }
        #pragma unroll
        for (int i = 0; i < 4; i++)
            #pragma unroll
            for (int j = 0; j < 4; j++) {
                float vv = acc[i][j] + b[tx * 4 + j];
                if (relu) vv = fmaxf(vv, 0.f);
                outp[(ty * 4 + i) * 65 + tx * 4 + j] = vv;
            }
    };

    // ===== path 0: rep_out @ W000 -> relu -> @W001 -> relu -> .Wo0 =====
    loadX((const float*)g_R);
    loadW(W000);
    __syncthreads();
    stage(U, V, b000, true);
    __syncthreads();
    loadW(W001);
    __syncthreads();
    stage(V, U, b001, true);
    if (tid < 64) sWv[tid] = Wo0[tid];
    __syncthreads();
    if (tid < 64) {
        float acc = 0.f;
        #pragma unroll 4
        for (int k = 0; k < 64; k++) acc += U[tid * 65 + k] * sWv[k];
        yy[0][tid] = acc;
    }
    __syncthreads();

    // ===== path 1 =====
    loadX((const float*)g_R);
    loadW(W100);
    __syncthreads();
    stage(U, V, b100, true);
    __syncthreads();
    loadW(W101);
    __syncthreads();
    stage(V, U, b101, true);
    if (tid < 64) sWv[tid] = Wo1[tid];
    __syncthreads();
    if (tid < 64) {
        float acc = 0.f;
        #pragma unroll 4
        for (int k = 0; k < 64; k++) acc += U[tid * 65 + k] * sWv[k];
        yy[1][tid] = acc;
    }
    __syncthreads();

    // ===== treatment head: rep_t @ Wpp + bpp (no relu), @ Wpp2, sigmoid =====
    loadX((const float*)g_D);
    loadW(Wpp);
    __syncthreads();
    stage(U, V, bpp, false);
    __syncthreads();

    if (tid < 64) {
        int row = r0 + tid;
        if (row < NN) {
            float z0 = 0.f, z1 = 0.f;
            #pragma unroll 4
            for (int k = 0; k < 64; k++) {
                float e = V[tid * 65 + k];
                z0 += e * Wpp2[k * 2];
                z1 += e * Wpp2[k * 2 + 1];
            }
            dout[650000 + (size_t)row * 2 + 0] = 1.f / (1.f + __expf(-(z0 + bpp2[0])));
            dout[650000 + (size_t)row * 2 + 1] = 1.f / (1.f + __expf(-(z1 + bpp2[1])));
            dout[row] = (t[row] > 0) ? (yy[1][tid] + bo1[0]) : (yy[0][tid] + bo0[0]);
        }
    }
    // re-arm edge pool for next graph replay
    if (blockIdx.x == 0 && tid == 0) g_top = 0;
}

// ---------------- launch ----------------
extern "C" void kernel_launch(void* const* d_in, const int* in_sizes, int n_in,
                              void* d_out, int out_size) {
    const float* x    = (const float*)d_in[0];
    const float* adj  = (const float*)d_in[1];
    const int*   t    = (const int*)d_in[2];
    const float* Wg0  = (const float*)d_in[3];
    const float* bg0  = (const float*)d_in[4];
    const float* Wg1  = (const float*)d_in[5];
    const float* bg1  = (const float*)d_in[6];
    const float* Wt0  = (const float*)d_in[7];
    const float* bt0  = (const float*)d_in[8];
    const float* Wt1  = (const float*)d_in[9];
    const float* bt1  = (const float*)d_in[10];
    const float* W000 = (const float*)d_in[11];
    const float* b000 = (const float*)d_in[12];
    const float* W001 = (const float*)d_in[13];
    const float* b001 = (const float*)d_in[14];
    const float* W100 = (const float*)d_in[15];
    const float* b100 = (const float*)d_in[16];
    const float* W101 = (const float*)d_in[17];
    const float* b101 = (const float*)d_in[18];
    const float* Wo0  = (const float*)d_in[19];
    const float* bo0  = (const float*)d_in[20];
    const float* Wo1  = (const float*)d_in[21];
    const float* bo1  = (const float*)d_in[22];
    const float* Wpp  = (const float*)d_in[23];
    const float* bpp  = (const float*)d_in[24];
    const float* Wpp2 = (const float*)d_in[25];
    const float* bpp2 = (const float*)d_in[26];
    const float* a    = (const float*)d_in[27];
    float* out = (float*)d_out;

    float* pA; cudaGetSymbolAddress((void**)&pA, g_A);
    float* pB; cudaGetSymbolAddress((void**)&pB, g_B);
    float* pC; cudaGetSymbolAddress((void**)&pC, g_C);
    float* pD; cudaGetSymbolAddress((void**)&pD, g_D);

    k_sparsify<<<NN, 256>>>(adj);

    // layer 1: P = x @ Wg0 / x @ Wt0
    {
        GemmArgs ga = {};
        ga.X[0] = x;   ga.X[1] = x;
        ga.W[0] = Wg0; ga.W[1] = Wt0;
        ga.out[0] = pA; ga.out[1] = pB;
        k_gemm<128><<<dim3(313, 2), 256>>>(ga);
    }
    k_spmm<<<NN, 64>>>(bg0, bt0, 0, nullptr);

    // layer 2
    {
        GemmArgs ga = {};
        ga.X[0] = pC;  ga.X[1] = pD;
        ga.W[0] = Wg1; ga.W[1] = Wt1;
        ga.out[0] = pA; ga.out[1] = pB;
        k_gemm<64><<<dim3(313, 2), 256>>>(ga);
    }
    k_spmm<<<NN, 64>>>(bg1, bt1, 1, a);   // + fused scores

    k_colsum_part<<<250, 64>>>();
    k_colsum_comb<<<1, 64>>>();
    k_att<<<5000, dim3(32, 2)>>>(out);

    k_heads<<<157, 256>>>(t, W000, b000, W001, b001, W100, b100, W101, b101,
                          Wo0, bo0, Wo1, bo1, Wpp, bpp, Wpp2, bpp2, out);
}

// round 9
// speedup vs baseline: 1.6334x; 1.0609x over previous
#include <cuda_runtime.h>
#include <math.h>

#define NN 10000
#define NN2 10048          // padded row count for scratch
#define NF 128
#define NH 64
#define MAXNNZ 2000000

// ---------------- scratch (device globals, no allocation) ----------------
__device__ __align__(16) float g_A[NN2 * NH];
__device__ __align__(16) float g_B[NN2 * NH];
__device__ __align__(16) float g_C[NN2 * NH];
__device__ __align__(16) float g_D[NN2 * NH];
__device__ __align__(16) float g_R[NN2 * NH];

struct __align__(8) Edge { int c; float v; };

__device__ int   g_rowbase[NN];
__device__ int   g_rownnz[NN];
__device__ Edge  g_edge[MAXNNZ];
__device__ int   g_top = 0;

__device__ __align__(16) float g_ssrc[NN];
__device__ __align__(16) float g_sdst[NN];
__device__ __align__(16) float g_part[250 * NH];
__device__ __align__(16) float g_Sall[NH];

struct GemmArgs {
    const float* X[2];
    const float* W[2];
    float*       out[2];
};

// ---------------- GEMM tile body: 32 rows x 64 cols, Xs transposed ----------------
// 256 threads: tx=tid&15 -> 4 adjacent cols, ty=tid>>4 -> 2 adjacent rows.
// Inner loop: 1 LDS.128 (weights) + 1 LDS.64 (x, transposed) per 8 FMA.
template <int K>
__device__ __forceinline__ void gemm_tile(const float* __restrict__ X,
                                          const float* __restrict__ W,
                                          float* __restrict__ O,
                                          int bx, int tid,
                                          float* Xs /*64*34*/, float* Ws /*64*64*/) {
    int tx = tid & 15, ty = tid >> 4;
    int r0 = bx * 32;
    float acc[2][4] = {};

    for (int k0 = 0; k0 < K; k0 += 64) {
        {   // weights chunk rows k0..k0+63 of [K,64]
            const float4* s = (const float4*)(W + (size_t)k0 * 64);
            float4* d = (float4*)Ws;
            #pragma unroll
            for (int i = 0; i < 4; i++) d[tid + 256 * i] = s[tid + 256 * i];
        }
        #pragma unroll
        for (int i = 0; i < 2; i++) {
            int e = tid + 256 * i;      // 0..511 f4 idx (32 rows x 16 f4)
            int row = e >> 4, c4 = e & 15;
            int rr = r0 + row;
            float4 v = make_float4(0.f, 0.f, 0.f, 0.f);
            if (rr < NN) v = ((const float4*)(X + (size_t)rr * K + k0))[c4];
            int kk = c4 * 4;
            Xs[(kk + 0) * 34 + row] = v.x;
            Xs[(kk + 1) * 34 + row] = v.y;
            Xs[(kk + 2) * 34 + row] = v.z;
            Xs[(kk + 3) * 34 + row] = v.w;
        }
        __syncthreads();
        #pragma unroll 8
        for (int k = 0; k < 64; k++) {
            float4 wv = *(const float4*)&Ws[k * 64 + tx * 4];
            float2 xv = *(const float2*)&Xs[k * 34 + ty * 2];
            acc[0][0] += xv.x * wv.x; acc[0][1] += xv.x * wv.y;
            acc[0][2] += xv.x * wv.z; acc[0][3] += xv.x * wv.w;
            acc[1][0] += xv.y * wv.x; acc[1][1] += xv.y * wv.y;
            acc[1][2] += xv.y * wv.z; acc[1][3] += xv.y * wv.w;
        }
        __syncthreads();
    }
    #pragma unroll
    for (int i = 0; i < 2; i++) {
        int rr = r0 + ty * 2 + i;
        if (rr >= NN) continue;
        float4 o = make_float4(acc[i][0], acc[i][1], acc[i][2], acc[i][3]);
        *(float4*)(O + (size_t)rr * 64 + tx * 4) = o;
    }
}

// ---------------- merged: sparsify (blocks 0..9999) + layer-1 GEMM (blocks 10000..10625) ----------------
__global__ void __launch_bounds__(256) k_spg(const float* __restrict__ adj, GemmArgs ga) {
    __shared__ float Xs[64 * 34];
    __shared__ float Ws[64 * 64];
    __shared__ int wsum[8];
    __shared__ int sbase;

    int t = threadIdx.x;

    if (blockIdx.x >= NN) {
        // ---- GEMM role: layer 1, K=128 ----
        int b = blockIdx.x - NN;        // 0..625
        int m = b >= 313;
        int bx = m ? b - 313 : b;
        gemm_tile<128>(ga.X[m], ga.W[m], ga.out[m], bx, t, Xs, Ws);
        return;
    }

    // ---- sparsify role ----
    int row = blockIdx.x;
    const float4* rp = (const float4*)(adj + (size_t)row * NN);
    int lane = t & 31, wid = t >> 5;

    float4 v[10];
    #pragma unroll
    for (int i = 0; i < 10; i++) {
        int j = t + 256 * i;
        if (j < NN / 4) v[i] = __ldcs(rp + j);
        else            v[i] = make_float4(0.f, 0.f, 0.f, 0.f);
    }

    int c = 0;
    #pragma unroll
    for (int i = 0; i < 10; i++)
        c += (v[i].x != 0.f) + (v[i].y != 0.f) + (v[i].z != 0.f) + (v[i].w != 0.f);

    int s = c;
    #pragma unroll
    for (int d = 1; d < 32; d <<= 1) {
        int n = __shfl_up_sync(0xffffffffu, s, d);
        if (lane >= d) s += n;
    }
    if (lane == 31) wsum[wid] = s;
    __syncthreads();
    int wbase = 0;
    #pragma unroll
    for (int i = 0; i < 8; i++) wbase += (i < wid) ? wsum[i] : 0;
    int excl = wbase + s - c;
    if (t == 0) {
        int tot = 0;
        #pragma unroll
        for (int i = 0; i < 8; i++) tot += wsum[i];
        int b = atomicAdd(&g_top, tot);
        g_rowbase[row] = b;
        g_rownnz[row]  = tot;
        sbase = b;
    }
    __syncthreads();

    int dst = sbase + excl;
    #pragma unroll
    for (int i = 0; i < 10; i++) {
        int cb = (t + 256 * i) * 4;
        if (v[i].x != 0.f) { g_edge[dst].c = cb + 0; g_edge[dst].v = v[i].x; dst++; }
        if (v[i].y != 0.f) { g_edge[dst].c = cb + 1; g_edge[dst].v = v[i].y; dst++; }
        if (v[i].z != 0.f) { g_edge[dst].c = cb + 2; g_edge[dst].v = v[i].z; dst++; }
        if (v[i].w != 0.f) { g_edge[dst].c = cb + 3; g_edge[dst].v = v[i].w; dst++; }
    }
}

// ---------------- standalone GEMM (layer 2) ----------------
template <int K>
__global__ void __launch_bounds__(256) k_gemm(GemmArgs ga) {
    __shared__ float Xs[64 * 34];
    __shared__ float Ws[64 * 64];
    int m = blockIdx.y;
    gemm_tile<K>(ga.X[m], ga.W[m], ga.out[m], blockIdx.x, threadIdx.x, Xs, Ws);
}

// ---------------- fused SpMM (+bias+relu), both paths per block; optional scores epilogue ----------------
__global__ void k_spmm(const float* __restrict__ b0, const float* __restrict__ b1,
                       int layer2, const float* __restrict__ a) {
    int row = blockIdx.x;
    int tid = threadIdx.x;          // 64
    int m = tid >> 5, l = tid & 31;
    const float2* __restrict__ P  = (const float2*)(m ? g_B : g_A);
    const float2* __restrict__ bb = (const float2*)(m ? b1 : b0);
    float2*       __restrict__ O  = (float2*)(m ? g_D : g_C);
    int base = g_rowbase[row], nnz = g_rownnz[row];

    __shared__ Edge  se[64];
    __shared__ float srep[128];
    __shared__ float xr[2], xd[2];

    float2 a0 = {0.f, 0.f}, a1 = {0.f, 0.f}, a2 = {0.f, 0.f}, a3 = {0.f, 0.f};
    for (int c0 = 0; c0 < nnz; c0 += 64) {
        int n = min(64, nnz - c0);
        if (tid < n) se[tid] = g_edge[base + c0 + tid];
        __syncthreads();
        int e = 0;
        for (; e + 4 <= n; e += 4) {
            Edge e0 = se[e], e1 = se[e + 1], e2 = se[e + 2], e3 = se[e + 3];
            float2 p0 = P[(size_t)e0.c * 32 + l];
            float2 p1 = P[(size_t)e1.c * 32 + l];
            float2 p2 = P[(size_t)e2.c * 32 + l];
            float2 p3 = P[(size_t)e3.c * 32 + l];
            a0.x += e0.v * p0.x; a0.y += e0.v * p0.y;
            a1.x += e1.v * p1.x; a1.y += e1.v * p1.y;
            a2.x += e2.v * p2.x; a2.y += e2.v * p2.y;
            a3.x += e3.v * p3.x; a3.y += e3.v * p3.y;
        }
        for (; e < n; e++) {
            Edge ee = se[e];
            float2 p = P[(size_t)ee.c * 32 + l];
            a0.x += ee.v * p.x; a0.y += ee.v * p.y;
        }
        __syncthreads();
    }
    float2 bv = bb[l];
    float2 acc;
    acc.x = fmaxf(a0.x + a1.x + a2.x + a3.x + bv.x, 0.f);
    acc.y = fmaxf(a0.y + a1.y + a2.y + a3.y + bv.y, 0.f);
    O[(size_t)row * 32 + l] = acc;

    if (layer2) {
        srep[m * 64 + 2 * l]     = acc.x;
        srep[m * 64 + 2 * l + 1] = acc.y;
        __syncthreads();
        float rs = srep[tid] * a[tid]       + srep[64 + tid] * a[64 + tid];
        float rd = srep[tid] * a[128 + tid] + srep[64 + tid] * a[192 + tid];
        #pragma unroll
        for (int o = 16; o; o >>= 1) {
            rs += __shfl_xor_sync(0xffffffffu, rs, o);
            rd += __shfl_xor_sync(0xffffffffu, rd, o);
        }
        if (l == 0) { xr[m] = rs; xd[m] = rd; }
        __syncthreads();
        if (tid == 0) { g_ssrc[row] = xr[0] + xr[1]; g_sdst[row] = xd[0] + xd[1]; }
    }
}

// ---------------- column sum of rep_t (deterministic 2-stage) ----------------
__global__ void k_colsum_part() {
    int b = blockIdx.x;   // 250 blocks x 40 rows
    int h = threadIdx.x;
    int r0 = b * 40;
    float acc = 0.f;
    #pragma unroll 4
    for (int r = r0; r < r0 + 40; r++) acc += g_D[(size_t)r * 64 + h];
    g_part[b * 64 + h] = acc;
}
__global__ void k_colsum_comb() {
    int h = threadIdx.x;
    float acc = 0.f;
    for (int b = 0; b < 250; b++) acc += g_part[b * 64 + h];
    g_Sall[h] = acc;
}

// ---------------- attention (analytic dense softmax over sparse scores), 1 warp/row ----------------
__global__ void k_att(float* __restrict__ dout) {
    int row = blockIdx.x * 2 + threadIdx.y;
    int l = threadIdx.x;
    int base = g_rowbase[row], nnz = g_rownnz[row];
    float si = g_ssrc[row];

    float lm = -1e30f;
    for (int e = l; e < nnz; e += 32)
        lm = fmaxf(lm, g_sdst[g_edge[base + e].c]);
    #pragma unroll
    for (int o = 16; o; o >>= 1)
        lm = fmaxf(lm, __shfl_xor_sync(0xffffffffu, lm, o));
    float mm = fmaxf(si + lm, 0.f);

    const float2* __restrict__ D2 = (const float2*)g_D;
    float2 aW = {0.f, 0.f}, aR = {0.f, 0.f};
    float sw = 0.f;
    for (int e = 0; e < nnz; e++) {
        int cc = g_edge[base + e].c;
        float w = __expf(si + g_sdst[cc] - mm);
        float2 p = D2[(size_t)cc * 32 + l];
        aW.x += w * p.x; aW.y += w * p.y;
        aR.x += p.x;     aR.y += p.y;
        sw += w;
    }
    float em = __expf(-mm);
    float denom = (float)(NN - nnz) * em + sw;
    float2 S = ((const float2*)g_Sall)[l];
    float2 C = ((const float2*)g_C)[(size_t)row * 32 + l];
    float2 v;
    v.x = (em * (S.x - aR.x) + aW.x) / denom + C.x;
    v.y = (em * (S.y - aR.y) + aW.y) / denom + C.y;
    ((float2*)(dout + 10000))[(size_t)row * 32 + l] = v;
    ((float2*)g_R)[(size_t)row * 32 + l] = v;
}

// ---------------- fused heads: all 5 small GEMMs + outputs, per 64-row tile ----------------
__global__ void __launch_bounds__(256) k_heads(
        const int* __restrict__ t,
        const float* __restrict__ W000, const float* __restrict__ b000,
        const float* __restrict__ W001, const float* __restrict__ b001,
        const float* __restrict__ W100, const float* __restrict__ b100,
        const float* __restrict__ W101, const float* __restrict__ b101,
        const float* __restrict__ Wo0,  const float* __restrict__ bo0,
        const float* __restrict__ Wo1,  const float* __restrict__ bo1,
        const float* __restrict__ Wpp,  const float* __restrict__ bpp,
        const float* __restrict__ Wpp2, const float* __restrict__ bpp2,
        float* __restrict__ dout) {
    __shared__ float U[64 * 65];
    __shared__ float V[64 * 65];
    __shared__ float Ws[64 * 64];
    __shared__ float sWv[64];
    __shared__ float yy[2][64];

    int tid = threadIdx.x;
    int tx = tid & 15, ty = tid >> 4;
    int r0 = blockIdx.x * 64;

    auto loadW = [&](const float* W) {
        const float4* s = (const float4*)W;
        float4* d = (float4*)Ws;
        #pragma unroll
        for (int i = 0; i < 4; i++) d[tid + 256 * i] = s[tid + 256 * i];
    };
    auto loadX = [&](const float* X) {
        #pragma unroll
        for (int i = 0; i < 4; i++) {
            int e = tid + 256 * i;
            int row = e >> 4, c4 = e & 15;
            float4 v = ((const float4*)(X + (size_t)(r0 + row) * 64))[c4];
            U[row * 65 + c4 * 4 + 0] = v.x;
            U[row * 65 + c4 * 4 + 1] = v.y;
            U[row * 65 + c4 * 4 + 2] = v.z;
            U[row * 65 + c4 * 4 + 3] = v.w;
        }
    };
    auto stage = [&](const float* in, float* outp, const float* b, bool relu) {
        float acc[4][4] = {};
        #pragma unroll 4
        for (int k = 0; k < 64; k++) {
            float4 wv = *(const float4*)&Ws[k * 64 + tx * 4];
            float xv[4];
            #pragma unroll
            for (int i = 0; i < 4; i++) xv[i] = in[(ty * 4 + i) * 65 + k];
            #pragma unroll
            for (int i = 0; i < 4; i++) {
                acc[i][0] += xv[i] * wv.x; acc[i][1] += xv[i] * wv.y;
                acc[i][2] += xv[i] * wv.z; acc[i][3] += xv[i] * wv.w;
            }
        }
        #pragma unroll
        for (int i = 0; i < 4; i++)
            #pragma unroll
            for (int j = 0; j < 4; j++) {
                float vv = acc[i][j] + b[tx * 4 + j];
                if (relu) vv = fmaxf(vv, 0.f);
                outp[(ty * 4 + i) * 65 + tx * 4 + j] = vv;
            }
    };

    // ===== path 0 =====
    loadX((const float*)g_R);
    loadW(W000);
    __syncthreads();
    stage(U, V, b000, true);
    __syncthreads();
    loadW(W001);
    __syncthreads();
    stage(V, U, b001, true);
    if (tid < 64) sWv[tid] = Wo0[tid];
    __syncthreads();
    if (tid < 64) {
        float acc = 0.f;
        #pragma unroll 4
        for (int k = 0; k < 64; k++) acc += U[tid * 65 + k] * sWv[k];
        yy[0][tid] = acc;
    }
    __syncthreads();

    // ===== path 1 =====
    loadX((const float*)g_R);
    loadW(W100);
    __syncthreads();
    stage(U, V, b100, true);
    __syncthreads();
    loadW(W101);
    __syncthreads();
    stage(V, U, b101, true);
    if (tid < 64) sWv[tid] = Wo1[tid];
    __syncthreads();
    if (tid < 64) {
        float acc = 0.f;
        #pragma unroll 4
        for (int k = 0; k < 64; k++) acc += U[tid * 65 + k] * sWv[k];
        yy[1][tid] = acc;
    }
    __syncthreads();

    // ===== treatment head =====
    loadX((const float*)g_D);
    loadW(Wpp);
    __syncthreads();
    stage(U, V, bpp, false);
    __syncthreads();

    if (tid < 64) {
        int row = r0 + tid;
        if (row < NN) {
            float z0 = 0.f, z1 = 0.f;
            #pragma unroll 4
            for (int k = 0; k < 64; k++) {
                float e = V[tid * 65 + k];
                z0 += e * Wpp2[k * 2];
                z1 += e * Wpp2[k * 2 + 1];
            }
            dout[650000 + (size_t)row * 2 + 0] = 1.f / (1.f + __expf(-(z0 + bpp2[0])));
            dout[650000 + (size_t)row * 2 + 1] = 1.f / (1.f + __expf(-(z1 + bpp2[1])));
            dout[row] = (t[row] > 0) ? (yy[1][tid] + bo1[0]) : (yy[0][tid] + bo0[0]);
        }
    }
    if (blockIdx.x == 0 && tid == 0) g_top = 0;
}

// ---------------- launch ----------------
extern "C" void kernel_launch(void* const* d_in, const int* in_sizes, int n_in,
                              void* d_out, int out_size) {
    const float* x    = (const float*)d_in[0];
    const float* adj  = (const float*)d_in[1];
    const int*   t    = (const int*)d_in[2];
    const float* Wg0  = (const float*)d_in[3];
    const float* bg0  = (const float*)d_in[4];
    const float* Wg1  = (const float*)d_in[5];
    const float* bg1  = (const float*)d_in[6];
    const float* Wt0  = (const float*)d_in[7];
    const float* bt0  = (const float*)d_in[8];
    const float* Wt1  = (const float*)d_in[9];
    const float* bt1  = (const float*)d_in[10];
    const float* W000 = (const float*)d_in[11];
    const float* b000 = (const float*)d_in[12];
    const float* W001 = (const float*)d_in[13];
    const float* b001 = (const float*)d_in[14];
    const float* W100 = (const float*)d_in[15];
    const float* b100 = (const float*)d_in[16];
    const float* W101 = (const float*)d_in[17];
    const float* b101 = (const float*)d_in[18];
    const float* Wo0  = (const float*)d_in[19];
    const float* bo0  = (const float*)d_in[20];
    const float* Wo1  = (const float*)d_in[21];
    const float* bo1  = (const float*)d_in[22];
    const float* Wpp  = (const float*)d_in[23];
    const float* bpp  = (const float*)d_in[24];
    const float* Wpp2 = (const float*)d_in[25];
    const float* bpp2 = (const float*)d_in[26];
    const float* a    = (const float*)d_in[27];
    float* out = (float*)d_out;

    float* pA; cudaGetSymbolAddress((void**)&pA, g_A);
    float* pB; cudaGetSymbolAddress((void**)&pB, g_B);
    float* pC; cudaGetSymbolAddress((void**)&pC, g_C);
    float* pD; cudaGetSymbolAddress((void**)&pD, g_D);

    // merged sparsify + layer-1 GEMM (independent work, one wave-filling launch)
    {
        GemmArgs ga = {};
        ga.X[0] = x;   ga.X[1] = x;
        ga.W[0] = Wg0; ga.W[1] = Wt0;
        ga.out[0] = pA; ga.out[1] = pB;
        k_spg<<<NN + 626, 256>>>(adj, ga);
    }
    k_spmm<<<NN, 64>>>(bg0, bt0, 0, nullptr);

    // layer 2
    {
        GemmArgs ga = {};
        ga.X[0] = pC;  ga.X[1] = pD;
        ga.W[0] = Wg1; ga.W[1] = Wt1;
        ga.out[0] = pA; ga.out[1] = pB;
        k_gemm<64><<<dim3(313, 2), 256>>>(ga);
    }
    k_spmm<<<NN, 64>>>(bg1, bt1, 1, a);   // + fused scores

    k_colsum_part<<<250, 64>>>();
    k_colsum_comb<<<1, 64>>>();
    k_att<<<5000, dim3(32, 2)>>>(out);

    k_heads<<<157, 256>>>(t, W000, b000, W001, b001, W100, b100, W101, b101,
                          Wo0, bo0, Wo1, bo1, Wpp, bpp, Wpp2, bpp2, out);
}

// round 10
// speedup vs baseline: 1.6644x; 1.0190x over previous
#include <cuda_runtime.h>
#include <math.h>

#define NN 10000
#define NN2 10048          // padded row count for scratch
#define NF 128
#define NH 64
#define MAXNNZ 2000000

// ---------------- scratch (device globals, no allocation) ----------------
// Interleaved layouts: row stride 128 floats; cols [0,64) = outcome path,
// cols [64,128) = treatment path.
__device__ __align__(16) float g_AB[NN2 * 128];   // P buffers (gemm out)
__device__ __align__(16) float g_CD[NN2 * 128];   // rep buffers (spmm out)
__device__ __align__(16) float g_R[NN2 * NH];     // rep_out

struct __align__(8) Edge { int c; float v; };

__device__ int   g_rowbase[NN];
__device__ int   g_rownnz[NN];
__device__ Edge  g_edge[MAXNNZ];
__device__ int   g_top = 0;

__device__ __align__(16) float g_ssrc[NN];
__device__ __align__(16) float g_sdst[NN];
__device__ __align__(16) float g_part[250 * NH];
__device__ __align__(16) float g_Sall[NH];

struct GemmArgs {
    const float* X[2];
    const float* W[2];
    float*       out[2];   // already offset by m*64; row stride 128
    int          xs;       // X row stride (floats)
};

// ---------------- GEMM tile body: 32 rows x 64 cols, Xs transposed ----------------
// 256 threads: tx=tid&15 -> 4 adjacent cols, ty=tid>>4 -> 2 adjacent rows.
template <int K>
__device__ __forceinline__ void gemm_tile(const float* __restrict__ X, int xstride,
                                          const float* __restrict__ W,
                                          float* __restrict__ O,
                                          int bx, int tid,
                                          float* Xs /*64*34*/, float* Ws /*64*64*/) {
    int tx = tid & 15, ty = tid >> 4;
    int r0 = bx * 32;
    float acc[2][4] = {};

    for (int k0 = 0; k0 < K; k0 += 64) {
        {   // weights chunk rows k0..k0+63 of [K,64]
            const float4* s = (const float4*)(W + (size_t)k0 * 64);
            float4* d = (float4*)Ws;
            #pragma unroll
            for (int i = 0; i < 4; i++) d[tid + 256 * i] = s[tid + 256 * i];
        }
        #pragma unroll
        for (int i = 0; i < 2; i++) {
            int e = tid + 256 * i;      // 0..511 f4 idx (32 rows x 16 f4)
            int row = e >> 4, c4 = e & 15;
            int rr = r0 + row;
            float4 v = make_float4(0.f, 0.f, 0.f, 0.f);
            if (rr < NN) v = ((const float4*)(X + (size_t)rr * xstride + k0))[c4];
            int kk = c4 * 4;
            Xs[(kk + 0) * 34 + row] = v.x;
            Xs[(kk + 1) * 34 + row] = v.y;
            Xs[(kk + 2) * 34 + row] = v.z;
            Xs[(kk + 3) * 34 + row] = v.w;
        }
        __syncthreads();
        #pragma unroll 8
        for (int k = 0; k < 64; k++) {
            float4 wv = *(const float4*)&Ws[k * 64 + tx * 4];
            float2 xv = *(const float2*)&Xs[k * 34 + ty * 2];
            acc[0][0] += xv.x * wv.x; acc[0][1] += xv.x * wv.y;
            acc[0][2] += xv.x * wv.z; acc[0][3] += xv.x * wv.w;
            acc[1][0] += xv.y * wv.x; acc[1][1] += xv.y * wv.y;
            acc[1][2] += xv.y * wv.z; acc[1][3] += xv.y * wv.w;
        }
        __syncthreads();
    }
    #pragma unroll
    for (int i = 0; i < 2; i++) {
        int rr = r0 + ty * 2 + i;
        if (rr >= NN) continue;
        float4 o = make_float4(acc[i][0], acc[i][1], acc[i][2], acc[i][3]);
        *(float4*)(O + (size_t)rr * 128 + tx * 4) = o;
    }
}

// ---------------- merged: sparsify (blocks 0..9999) + layer-1 GEMM ----------------
__global__ void __launch_bounds__(256) k_spg(const float* __restrict__ adj, GemmArgs ga) {
    __shared__ float Xs[64 * 34];
    __shared__ float Ws[64 * 64];
    __shared__ int wsum[8];
    __shared__ int sbase;

    int t = threadIdx.x;

    if (blockIdx.x >= NN) {
        int b = blockIdx.x - NN;        // 0..625
        int m = b >= 313;
        int bx = m ? b - 313 : b;
        gemm_tile<128>(ga.X[m], ga.xs, ga.W[m], ga.out[m], bx, t, Xs, Ws);
        return;
    }

    // ---- sparsify role ----
    int row = blockIdx.x;
    const float4* rp = (const float4*)(adj + (size_t)row * NN);
    int lane = t & 31, wid = t >> 5;

    float4 v[10];
    #pragma unroll
    for (int i = 0; i < 10; i++) {
        int j = t + 256 * i;
        if (j < NN / 4) v[i] = __ldcs(rp + j);
        else            v[i] = make_float4(0.f, 0.f, 0.f, 0.f);
    }

    int c = 0;
    #pragma unroll
    for (int i = 0; i < 10; i++)
        c += (v[i].x != 0.f) + (v[i].y != 0.f) + (v[i].z != 0.f) + (v[i].w != 0.f);

    int s = c;
    #pragma unroll
    for (int d = 1; d < 32; d <<= 1) {
        int n = __shfl_up_sync(0xffffffffu, s, d);
        if (lane >= d) s += n;
    }
    if (lane == 31) wsum[wid] = s;
    __syncthreads();
    int wbase = 0;
    #pragma unroll
    for (int i = 0; i < 8; i++) wbase += (i < wid) ? wsum[i] : 0;
    int excl = wbase + s - c;
    if (t == 0) {
        int tot = 0;
        #pragma unroll
        for (int i = 0; i < 8; i++) tot += wsum[i];
        int b = atomicAdd(&g_top, tot);
        g_rowbase[row] = b;
        g_rownnz[row]  = tot;
        sbase = b;
    }
    __syncthreads();

    int dst = sbase + excl;
    #pragma unroll
    for (int i = 0; i < 10; i++) {
        int cb = (t + 256 * i) * 4;
        if (v[i].x != 0.f) { g_edge[dst].c = cb + 0; g_edge[dst].v = v[i].x; dst++; }
        if (v[i].y != 0.f) { g_edge[dst].c = cb + 1; g_edge[dst].v = v[i].y; dst++; }
        if (v[i].z != 0.f) { g_edge[dst].c = cb + 2; g_edge[dst].v = v[i].z; dst++; }
        if (v[i].w != 0.f) { g_edge[dst].c = cb + 3; g_edge[dst].v = v[i].w; dst++; }
    }
}

// ---------------- standalone GEMM (layer 2) ----------------
template <int K>
__global__ void __launch_bounds__(256) k_gemm(GemmArgs ga) {
    __shared__ float Xs[64 * 34];
    __shared__ float Ws[64 * 64];
    int m = blockIdx.y;
    gemm_tile<K>(ga.X[m], ga.xs, ga.W[m], ga.out[m], blockIdx.x, threadIdx.x, Xs, Ws);
}

// ---------------- fused SpMM (+bias+relu), both paths via interleaved float4 ----------------
// 64 threads = 2 warps; one warp covers BOTH paths per edge (32 lanes x float4 = 512B);
// the 2 warps process alternating edges. Cross-warp float4 reduce at the end.
__global__ void k_spmm(const float* __restrict__ b0, const float* __restrict__ b1,
                       int layer2, const float* __restrict__ a) {
    int row = blockIdx.x;
    int tid = threadIdx.x;          // 64
    int w = tid >> 5, l = tid & 31;
    int base = g_rowbase[row], nnz = g_rownnz[row];
    const float4* __restrict__ AB4 = (const float4*)g_AB;

    __shared__ Edge se[64];
    __shared__ __align__(16) float sbias[128];
    __shared__ float4 red[32];
    __shared__ __align__(16) float srep[128];
    __shared__ float xr[2], xd[2];

    sbias[tid]      = b0[tid];
    sbias[tid + 64] = b1[tid];

    float4 acc[4];
    #pragma unroll
    for (int u = 0; u < 4; u++) acc[u] = make_float4(0.f, 0.f, 0.f, 0.f);

    for (int c0 = 0; c0 < nnz; c0 += 64) {
        int n = min(64, nnz - c0);
        if (tid < n) se[tid] = g_edge[base + c0 + tid];
        __syncthreads();
        int e = w;
        for (; e + 6 < n; e += 8) {
            #pragma unroll
            for (int u = 0; u < 4; u++) {
                Edge ed = se[e + 2 * u];
                float4 p = AB4[(size_t)ed.c * 32 + l];
                acc[u].x += ed.v * p.x; acc[u].y += ed.v * p.y;
                acc[u].z += ed.v * p.z; acc[u].w += ed.v * p.w;
            }
        }
        for (; e < n; e += 2) {
            Edge ed = se[e];
            float4 p = AB4[(size_t)ed.c * 32 + l];
            acc[0].x += ed.v * p.x; acc[0].y += ed.v * p.y;
            acc[0].z += ed.v * p.z; acc[0].w += ed.v * p.w;
        }
        __syncthreads();
    }
    float4 sum;
    sum.x = acc[0].x + acc[1].x + acc[2].x + acc[3].x;
    sum.y = acc[0].y + acc[1].y + acc[2].y + acc[3].y;
    sum.z = acc[0].z + acc[1].z + acc[2].z + acc[3].z;
    sum.w = acc[0].w + acc[1].w + acc[2].w + acc[3].w;

    if (w == 1) red[l] = sum;
    __syncthreads();
    if (w == 0) {
        float4 o = red[l];
        float4 bv = *(const float4*)&sbias[l * 4];
        sum.x = fmaxf(sum.x + o.x + bv.x, 0.f);
        sum.y = fmaxf(sum.y + o.y + bv.y, 0.f);
        sum.z = fmaxf(sum.z + o.z + bv.z, 0.f);
        sum.w = fmaxf(sum.w + o.w + bv.w, 0.f);
        ((float4*)g_CD)[(size_t)row * 32 + l] = sum;
        if (layer2) *(float4*)&srep[l * 4] = sum;
    }

    if (layer2) {
        __syncthreads();
        float rs = srep[tid] * a[tid]       + srep[64 + tid] * a[64 + tid];
        float rd = srep[tid] * a[128 + tid] + srep[64 + tid] * a[192 + tid];
        #pragma unroll
        for (int o = 16; o; o >>= 1) {
            rs += __shfl_xor_sync(0xffffffffu, rs, o);
            rd += __shfl_xor_sync(0xffffffffu, rd, o);
        }
        if (l == 0) { xr[w] = rs; xd[w] = rd; }
        __syncthreads();
        if (tid == 0) { g_ssrc[row] = xr[0] + xr[1]; g_sdst[row] = xd[0] + xd[1]; }
    }
}

// ---------------- column sum of rep_t (deterministic 2-stage) ----------------
__global__ void k_colsum_part() {
    int b = blockIdx.x;   // 250 blocks x 40 rows
    int h = threadIdx.x;
    int r0 = b * 40;
    float acc = 0.f;
    #pragma unroll 4
    for (int r = r0; r < r0 + 40; r++) acc += g_CD[(size_t)r * 128 + 64 + h];
    g_part[b * 64 + h] = acc;
}
__global__ void k_colsum_comb() {
    int h = threadIdx.x;
    float acc = 0.f;
    for (int b = 0; b < 250; b++) acc += g_part[b * 64 + h];
    g_Sall[h] = acc;
}

// ---------------- attention: half-warp float4 gather, 2 edges per warp-iter ----------------
__global__ void k_att(float* __restrict__ dout) {
    int row = blockIdx.x * 2 + threadIdx.y;
    int l = threadIdx.x;
    int half = l >> 4, q = l & 15;
    int base = g_rowbase[row], nnz = g_rownnz[row];
    float si = g_ssrc[row];

    float lm = -1e30f;
    for (int e = l; e < nnz; e += 32)
        lm = fmaxf(lm, g_sdst[g_edge[base + e].c]);
    #pragma unroll
    for (int o = 16; o; o >>= 1)
        lm = fmaxf(lm, __shfl_xor_sync(0xffffffffu, lm, o));
    float mm = fmaxf(si + lm, 0.f);

    const float4* __restrict__ CD4 = (const float4*)g_CD;
    float4 aW0 = {0.f,0.f,0.f,0.f}, aW1 = aW0, aR0 = aW0, aR1 = aW0;
    float sw = 0.f;
    int e = half;
    for (; e + 2 < nnz; e += 4) {
        int c0 = g_edge[base + e].c;
        int c1 = g_edge[base + e + 2].c;
        float w0 = __expf(si + g_sdst[c0] - mm);
        float w1 = __expf(si + g_sdst[c1] - mm);
        float4 p0 = CD4[(size_t)c0 * 32 + 16 + q];
        float4 p1 = CD4[(size_t)c1 * 32 + 16 + q];
        aW0.x += w0 * p0.x; aW0.y += w0 * p0.y; aW0.z += w0 * p0.z; aW0.w += w0 * p0.w;
        aW1.x += w1 * p1.x; aW1.y += w1 * p1.y; aW1.z += w1 * p1.z; aW1.w += w1 * p1.w;
        aR0.x += p0.x; aR0.y += p0.y; aR0.z += p0.z; aR0.w += p0.w;
        aR1.x += p1.x; aR1.y += p1.y; aR1.z += p1.z; aR1.w += p1.w;
        sw += w0 + w1;
    }
    for (; e < nnz; e += 2) {
        int cc = g_edge[base + e].c;
        float wt = __expf(si + g_sdst[cc] - mm);
        float4 p = CD4[(size_t)cc * 32 + 16 + q];
        aW0.x += wt * p.x; aW0.y += wt * p.y; aW0.z += wt * p.z; aW0.w += wt * p.w;
        aR0.x += p.x; aR0.y += p.y; aR0.z += p.z; aR0.w += p.w;
        sw += wt;
    }
    float4 aW, aR;
    aW.x = aW0.x + aW1.x; aW.y = aW0.y + aW1.y; aW.z = aW0.z + aW1.z; aW.w = aW0.w + aW1.w;
    aR.x = aR0.x + aR1.x; aR.y = aR0.y + aR1.y; aR.z = aR0.z + aR1.z; aR.w = aR0.w + aR1.w;

    // combine the two halves (each half's lanes carry identical sw)
    sw   += __shfl_xor_sync(0xffffffffu, sw, 16);
    aW.x += __shfl_xor_sync(0xffffffffu, aW.x, 16);
    aW.y += __shfl_xor_sync(0xffffffffu, aW.y, 16);
    aW.z += __shfl_xor_sync(0xffffffffu, aW.z, 16);
    aW.w += __shfl_xor_sync(0xffffffffu, aW.w, 16);
    aR.x += __shfl_xor_sync(0xffffffffu, aR.x, 16);
    aR.y += __shfl_xor_sync(0xffffffffu, aR.y, 16);
    aR.z += __shfl_xor_sync(0xffffffffu, aR.z, 16);
    aR.w += __shfl_xor_sync(0xffffffffu, aR.w, 16);

    float em = __expf(-mm);
    float denom = (float)(NN - nnz) * em + sw;
    if (half == 0) {
        float4 S = ((const float4*)g_Sall)[q];
        float4 C = CD4[(size_t)row * 32 + q];
        float4 v;
        v.x = (em * (S.x - aR.x) + aW.x) / denom + C.x;
        v.y = (em * (S.y - aR.y) + aW.y) / denom + C.y;
        v.z = (em * (S.z - aR.z) + aW.z) / denom + C.z;
        v.w = (em * (S.w - aR.w) + aW.w) / denom + C.w;
        ((float4*)(dout + 10000))[(size_t)row * 16 + q] = v;
        ((float4*)g_R)[(size_t)row * 16 + q] = v;
    }
}

// ---------------- fused heads: all 5 small GEMMs + outputs, per 64-row tile ----------------
__global__ void __launch_bounds__(256) k_heads(
        const int* __restrict__ t,
        const float* __restrict__ W000, const float* __restrict__ b000,
        const float* __restrict__ W001, const float* __restrict__ b001,
        const float* __restrict__ W100, const float* __restrict__ b100,
        const float* __restrict__ W101, const float* __restrict__ b101,
        const float* __restrict__ Wo0,  const float* __restrict__ bo0,
        const float* __restrict__ Wo1,  const float* __restrict__ bo1,
        const float* __restrict__ Wpp,  const float* __restrict__ bpp,
        const float* __restrict__ Wpp2, const float* __restrict__ bpp2,
        float* __restrict__ dout) {
    __shared__ float U[64 * 65];
    __shared__ float V[64 * 65];
    __shared__ float Ws[64 * 64];
    __shared__ float sWv[64];
    __shared__ float yy[2][64];

    int tid = threadIdx.x;
    int tx = tid & 15, ty = tid >> 4;
    int r0 = blockIdx.x * 64;

    auto loadW = [&](const float* W) {
        const float4* s = (const float4*)W;
        float4* d = (float4*)Ws;
        #pragma unroll
        for (int i = 0; i < 4; i++) d[tid + 256 * i] = s[tid + 256 * i];
    };
    auto loadX = [&](const float* X, int stride) {
        #pragma unroll
        for (int i = 0; i < 4; i++) {
            int e = tid + 256 * i;
            int row = e >> 4, c4 = e & 15;
            float4 v = ((const float4*)(X + (size_t)(r0 + row) * stride))[c4];
            U[row * 65 + c4 * 4 + 0] = v.x;
            U[row * 65 + c4 * 4 + 1] = v.y;
            U[row * 65 + c4 * 4 + 2] = v.z;
            U[row * 65 + c4 * 4 + 3] = v.w;
        }
    };
    auto stage = [&](const float* in, float* outp, const float* b, bool relu) {
        float acc[4][4] = {};
        #pragma unroll 4
        for (int k = 0; k < 64; k++) {
            float4 wv = *(const float4*)&Ws[k * 64 + tx * 4];
            float xv[4];
            #pragma unroll
            for (int i = 0; i < 4; i++) xv[i] = in[(ty * 4 + i) * 65 + k];
            #pragma unroll
            for (int i = 0; i < 4; i++) {
                acc[i][0] += xv[i] * wv.x; acc[i][1] += xv[i] * wv.y;
                acc[i][2] += xv[i] * wv.z; acc[i][3] += xv[i] * wv.w;
            }
        }
        #pragma unroll
        for (int i = 0; i < 4; i++)
            #pragma unroll
            for (int j = 0; j < 4; j++) {
                float vv = acc[i][j] + b[tx * 4 + j];
                if (relu) vv = fmaxf(vv, 0.f);
                outp[(ty * 4 + i) * 65 + tx * 4 + j] = vv;
            }
    };

    // ===== path 0 =====
    loadX((const float*)g_R, 64);
    loadW(W000);
    __syncthreads();
    stage(U, V, b000, true);
    __syncthreads();
    loadW(W001);
    __syncthreads();
    stage(V, U, b001, true);
    if (tid < 64) sWv[tid] = Wo0[tid];
    __syncthreads();
    if (tid < 64) {
        float acc = 0.f;
        #pragma unroll 4
        for (int k = 0; k < 64; k++) acc += U[tid * 65 + k] * sWv[k];
        yy[0][tid] = acc;
    }
    __syncthreads();

    // ===== path 1 =====
    loadX((const float*)g_R, 64);
    loadW(W100);
    __syncthreads();
    stage(U, V, b100, true);
    __syncthreads();
    loadW(W101);
    __syncthreads();
    stage(V, U, b101, true);
    if (tid < 64) sWv[tid] = Wo1[tid];
    __syncthreads();
    if (tid < 64) {
        float acc = 0.f;
        #pragma unroll 4
        for (int k = 0; k < 64; k++) acc += U[tid * 65 + k] * sWv[k];
        yy[1][tid] = acc;
    }
    __syncthreads();

    // ===== treatment head =====
    loadX((const float*)g_CD + 64, 128);
    loadW(Wpp);
    __syncthreads();
    stage(U, V, bpp, false);
    __syncthreads();

    if (tid < 64) {
        int row = r0 + tid;
        if (row < NN) {
            float z0 = 0.f, z1 = 0.f;
            #pragma unroll 4
            for (int k = 0; k < 64; k++) {
                float e = V[tid * 65 + k];
                z0 += e * Wpp2[k * 2];
                z1 += e * Wpp2[k * 2 + 1];
            }
            dout[650000 + (size_t)row * 2 + 0] = 1.f / (1.f + __expf(-(z0 + bpp2[0])));
            dout[650000 + (size_t)row * 2 + 1] = 1.f / (1.f + __expf(-(z1 + bpp2[1])));
            dout[row] = (t[row] > 0) ? (yy[1][tid] + bo1[0]) : (yy[0][tid] + bo0[0]);
        }
    }
    if (blockIdx.x == 0 && tid == 0) g_top = 0;
}

// ---------------- launch ----------------
extern "C" void kernel_launch(void* const* d_in, const int* in_sizes, int n_in,
                              void* d_out, int out_size) {
    const float* x    = (const float*)d_in[0];
    const float* adj  = (const float*)d_in[1];
    const int*   t    = (const int*)d_in[2];
    const float* Wg0  = (const float*)d_in[3];
    const float* bg0  = (const float*)d_in[4];
    const float* Wg1  = (const float*)d_in[5];
    const float* bg1  = (const float*)d_in[6];
    const float* Wt0  = (const float*)d_in[7];
    const float* bt0  = (const float*)d_in[8];
    const float* Wt1  = (const float*)d_in[9];
    const float* bt1  = (const float*)d_in[10];
    const float* W000 = (const float*)d_in[11];
    const float* b000 = (const float*)d_in[12];
    const float* W001 = (const float*)d_in[13];
    const float* b001 = (const float*)d_in[14];
    const float* W100 = (const float*)d_in[15];
    const float* b100 = (const float*)d_in[16];
    const float* W101 = (const float*)d_in[17];
    const float* b101 = (const float*)d_in[18];
    const float* Wo0  = (const float*)d_in[19];
    const float* bo0  = (const float*)d_in[20];
    const float* Wo1  = (const float*)d_in[21];
    const float* bo1  = (const float*)d_in[22];
    const float* Wpp  = (const float*)d_in[23];
    const float* bpp  = (const float*)d_in[24];
    const float* Wpp2 = (const float*)d_in[25];
    const float* bpp2 = (const float*)d_in[26];
    const float* a    = (const float*)d_in[27];
    float* out = (float*)d_out;

    float* pAB; cudaGetSymbolAddress((void**)&pAB, g_AB);
    float* pCD; cudaGetSymbolAddress((void**)&pCD, g_CD);

    // merged sparsify + layer-1 GEMM
    {
        GemmArgs ga = {};
        ga.X[0] = x;   ga.X[1] = x;
        ga.W[0] = Wg0; ga.W[1] = Wt0;
        ga.out[0] = pAB; ga.out[1] = pAB + 64;
        ga.xs = 128;
        k_spg<<<NN + 626, 256>>>(adj, ga);
    }
    k_spmm<<<NN, 64>>>(bg0, bt0, 0, nullptr);

    // layer 2
    {
        GemmArgs ga = {};
        ga.X[0] = pCD;  ga.X[1] = pCD + 64;
        ga.W[0] = Wg1; ga.W[1] = Wt1;
        ga.out[0] = pAB; ga.out[1] = pAB + 64;
        ga.xs = 128;
        k_gemm<64><<<dim3(313, 2), 256>>>(ga);
    }
    k_spmm<<<NN, 64>>>(bg1, bt1, 1, a);   // + fused scores

    k_colsum_part<<<250, 64>>>();
    k_colsum_comb<<<1, 64>>>();
    k_att<<<5000, dim3(32, 2)>>>(out);

    k_heads<<<157, 256>>>(t, W000, b000, W001, b001, W100, b100, W101, b101,
                          Wo0, bo0, Wo1, bo1, Wpp, bpp, Wpp2, bpp2, out);
}